// round 1
// baseline (speedup 1.0000x reference)
#include <cuda_runtime.h>
#include <math.h>

#define IN_DIM  256
#define HID     64
#define HEADS   4
#define FTOT    256     // HEADS*HID
#define OUT_DIM 10
#define NGRAPH  64
#define MAXN    50000
#define MAXE    800000

// ---------------- static scratch (allocation-free rule) ----------------
__device__ float    g_feat[MAXN * FTOT];   // h1, then elu(h1_out)
__device__ float    g_lin [MAXN * FTOT];   // h2 linear output
__device__ float    g_acc [MAXN * FTOT];   // aggregation accumulator
__device__ float    g_as  [MAXN * HEADS];
__device__ float    g_ad  [MAXN * HEADS];
__device__ float    g_e   [(MAXE + MAXN) * HEADS];
__device__ unsigned g_m   [MAXN * HEADS];
__device__ float    g_den [MAXN * HEADS];
__device__ int      g_srcdst[2 * MAXE];    // [src(E), dst(E)] int32-normalized
__device__ int      g_batch [MAXN];
__device__ float    g_pooled[NGRAPH * HID];
__device__ float    g_cnt   [NGRAPH];

// ---------------- helpers ----------------
__device__ __forceinline__ unsigned fenc(float f) {
    unsigned u = __float_as_uint(f);
    return (u & 0x80000000u) ? ~u : (u | 0x80000000u);
}
__device__ __forceinline__ float fdec(unsigned k) {
    return (k & 0x80000000u) ? __uint_as_float(k & 0x7FFFFFFFu)
                             : __uint_as_float(~k);
}
__device__ __forceinline__ void red_add_f4(float* addr, float4 v) {
    asm volatile("red.global.add.v4.f32 [%0], {%1, %2, %3, %4};"
                 :: "l"(addr), "f"(v.x), "f"(v.y), "f"(v.z), "f"(v.w)
                 : "memory");
}
__device__ __forceinline__ float elu1(float x) {
    return x > 0.f ? x : expm1f(x);
}

// ---------------- dtype-normalizing converters ----------------
// Detect whether raw data is int64 (odd 32-bit words = high halves = 0) or int32.
__global__ void convert_edges_kernel(const int* __restrict__ raw, int count /*=2E*/) {
    int nz = (raw[2 * threadIdx.x + 1] != 0);       // probe words 1,3,...,511
    int any = __syncthreads_or(nz);
    int is64 = !any;
    for (int v = blockIdx.x * blockDim.x + threadIdx.x; v < count;
         v += gridDim.x * blockDim.x)
        g_srcdst[v] = is64 ? raw[2 * v] : raw[v];
}

__global__ void convert_batch_kernel(const int* __restrict__ raw, int count /*=N*/) {
    // batch is SORTED; the front is all zeros either way, so probe odd words in
    // the second half: int64 high-halves -> 0; int32 values there are ~graph 32+.
    int base = count / 2;
    int w = (base | 1) + 2 * threadIdx.x;           // odd index >= count/2
    int nz = (raw[w] != 0);
    int any = __syncthreads_or(nz);
    int is64 = !any;
    for (int v = blockIdx.x * blockDim.x + threadIdx.x; v < count;
         v += gridDim.x * blockDim.x)
        g_batch[v] = is64 ? raw[2 * v] : raw[v];
}

// ---------------- zero kernels ----------------
__global__ void zero_acc_kernel(int n4) {
    int i = blockIdx.x * blockDim.x + threadIdx.x;
    if (i < n4) reinterpret_cast<float4*>(g_acc)[i] = make_float4(0.f, 0.f, 0.f, 0.f);
}
__global__ void zero_small_kernel(int nh) {
    int i = blockIdx.x * blockDim.x + threadIdx.x;
    if (i < nh) { g_m[i] = 0u; g_den[i] = 0.f; }
    if (i < NGRAPH * HID) g_pooled[i] = 0.f;
    if (i < NGRAPH) g_cnt[i] = 0.f;
}

// ---------------- fp32 tiled GEMM: C[M,256] = A[M,256] @ B[256,256] ----------------
// BM=128, BN=64, BK=16, 256 threads, 8x4 microtile.
__global__ __launch_bounds__(256) void gemm_kernel(
    const float* __restrict__ Aext, const float* __restrict__ B, int M, int which)
{
    const float* __restrict__ A = which ? g_feat : Aext;
    float* __restrict__ C = which ? g_lin : g_feat;

    __shared__ float As[16][128];
    __shared__ float Bs[16][64];

    int t  = threadIdx.x;
    int m0 = blockIdx.y * 128;
    int n0 = blockIdx.x * 64;
    int tx = t & 15;          // column group (4 cols)
    int ty = t >> 4;          // row group (8 rows)

    float acc[8][4];
    #pragma unroll
    for (int i = 0; i < 8; i++)
        #pragma unroll
        for (int j = 0; j < 4; j++) acc[i][j] = 0.f;

    int brow = t >> 4;
    int bcq  = (t & 15) * 4;

    for (int k0 = 0; k0 < 256; k0 += 16) {
        // load A tile (128x16), transposed into As[k][m]
        #pragma unroll
        for (int r = 0; r < 2; r++) {
            int id   = t + r * 256;
            int arow = id >> 2;
            int akq  = (id & 3) * 4;
            float4 a4 = make_float4(0.f, 0.f, 0.f, 0.f);
            int grow = m0 + arow;
            if (grow < M)
                a4 = *reinterpret_cast<const float4*>(&A[grow * 256 + k0 + akq]);
            As[akq + 0][arow] = a4.x;
            As[akq + 1][arow] = a4.y;
            As[akq + 2][arow] = a4.z;
            As[akq + 3][arow] = a4.w;
        }
        // load B tile (16x64)
        float4 b4 = *reinterpret_cast<const float4*>(&B[(k0 + brow) * 256 + n0 + bcq]);
        *reinterpret_cast<float4*>(&Bs[brow][bcq]) = b4;
        __syncthreads();

        #pragma unroll
        for (int k = 0; k < 16; k++) {
            float4 a0 = *reinterpret_cast<const float4*>(&As[k][ty * 8]);
            float4 a1 = *reinterpret_cast<const float4*>(&As[k][ty * 8 + 4]);
            float4 bb = *reinterpret_cast<const float4*>(&Bs[k][tx * 4]);
            float av[8] = {a0.x, a0.y, a0.z, a0.w, a1.x, a1.y, a1.z, a1.w};
            float bv[4] = {bb.x, bb.y, bb.z, bb.w};
            #pragma unroll
            for (int i = 0; i < 8; i++)
                #pragma unroll
                for (int j = 0; j < 4; j++)
                    acc[i][j] = fmaf(av[i], bv[j], acc[i][j]);
        }
        __syncthreads();
    }

    #pragma unroll
    for (int i = 0; i < 8; i++) {
        int row = m0 + ty * 8 + i;
        if (row < M)
            *reinterpret_cast<float4*>(&C[row * 256 + n0 + tx * 4]) =
                make_float4(acc[i][0], acc[i][1], acc[i][2], acc[i][3]);
    }
}

// ---------------- per-node attention coefficients ----------------
// one warp per (node, head): alpha_s/d = dot(h[n,h,:], att[h,:])
__global__ __launch_bounds__(256) void alphas_kernel(
    const float* __restrict__ att_s, const float* __restrict__ att_d, int N, int which)
{
    const float* __restrict__ h = which ? g_lin : g_feat;
    int w    = (blockIdx.x * blockDim.x + threadIdx.x) >> 5;
    int lane = threadIdx.x & 31;
    if (w >= N * HEADS) return;
    int n = w >> 2, hh = w & 3;
    const float* row = h + n * FTOT + hh * HID;
    const float* sv  = att_s + hh * HID;
    const float* dv  = att_d + hh * HID;
    float s = row[lane] * sv[lane] + row[lane + 32] * sv[lane + 32];
    float d = row[lane] * dv[lane] + row[lane + 32] * dv[lane + 32];
    #pragma unroll
    for (int o = 16; o; o >>= 1) {
        s += __shfl_down_sync(0xFFFFFFFFu, s, o);
        d += __shfl_down_sync(0xFFFFFFFFu, d, o);
    }
    if (lane == 0) { g_as[w] = s; g_ad[w] = d; }
}

// ---------------- edge pass 1: leaky logits + segment max ----------------
__global__ __launch_bounds__(256) void edge_logits_kernel(int E, int Etot) {
    int idx = blockIdx.x * blockDim.x + threadIdx.x;
    if (idx >= Etot * HEADS) return;
    int e = idx >> 2, h = idx & 3;
    int s, d;
    if (e < E) { s = g_srcdst[e]; d = g_srcdst[E + e]; }
    else       { s = d = e - E; }
    float v = g_as[s * HEADS + h] + g_ad[d * HEADS + h];
    v = v > 0.f ? v : 0.2f * v;
    g_e[idx] = v;
    atomicMax(&g_m[d * HEADS + h], fenc(v));
}

// ---------------- edge pass 2: exp + segment sum ----------------
__global__ __launch_bounds__(256) void edge_exp_kernel(int E, int Etot) {
    int idx = blockIdx.x * blockDim.x + threadIdx.x;
    if (idx >= Etot * HEADS) return;
    int e = idx >> 2, h = idx & 3;
    int d = (e < E) ? g_srcdst[E + e] : (e - E);
    float ee = expf(g_e[idx] - fdec(g_m[d * HEADS + h]));
    g_e[idx] = ee;
    atomicAdd(&g_den[d * HEADS + h], ee);
}

// ---------------- edge pass 3: weighted scatter-add ----------------
// 64 threads per edge, float4 per thread, vector global reduction.
__global__ __launch_bounds__(256) void edge_agg_kernel(int E, int Etot, int which) {
    const float* __restrict__ h = which ? g_lin : g_feat;
    int gtid = blockIdx.x * blockDim.x + threadIdx.x;
    int e = gtid >> 6;
    if (e >= Etot) return;
    int j = gtid & 63;                         // float4 slot (covers 256 cols)
    int s, d;
    if (e < E) { s = g_srcdst[e]; d = g_srcdst[E + e]; }
    else       { s = d = e - E; }
    int hh = j >> 4;                           // head of this slot
    float alpha = g_e[e * HEADS + hh] / (g_den[d * HEADS + hh] + 1e-16f);
    float4 hv = *reinterpret_cast<const float4*>(&h[s * FTOT + j * 4]);
    red_add_f4(&g_acc[d * FTOT + j * 4],
               make_float4(hv.x * alpha, hv.y * alpha, hv.z * alpha, hv.w * alpha));
}

// ---------------- bias + ELU (layer-1 epilogue) ----------------
__global__ __launch_bounds__(256) void bias_elu_kernel(const float* __restrict__ b, int total) {
    int i = blockIdx.x * blockDim.x + threadIdx.x;
    if (i >= total) return;
    g_feat[i] = elu1(g_acc[i] + b[i & (FTOT - 1)]);
}

// ---------------- head mean + bias + ELU + graph pooling ----------------
__global__ __launch_bounds__(256) void head_pool_kernel(const float* __restrict__ b2, int N) {
    int idx = blockIdx.x * blockDim.x + threadIdx.x;
    if (idx >= N * HID) return;
    int n = idx >> 6, c = idx & 63;
    const float* r = g_acc + n * FTOT;
    float v = 0.25f * (r[c] + r[HID + c] + r[2 * HID + c] + r[3 * HID + c]) + b2[c];
    v = elu1(v);
    int g = g_batch[n];
    atomicAdd(&g_pooled[g * HID + c], v);
    if (c == 0) atomicAdd(&g_cnt[g], 1.0f);
}

// ---------------- classifier + log_softmax ----------------
__global__ void final_kernel(const float* __restrict__ fcw, const float* __restrict__ fcb,
                             float* __restrict__ out) {
    int g = threadIdx.x;
    if (g >= NGRAPH) return;
    float inv = 1.f / fmaxf(g_cnt[g], 1.f);
    float l[OUT_DIM];
    #pragma unroll
    for (int o = 0; o < OUT_DIM; o++) l[o] = fcb[o];
    for (int c = 0; c < HID; c++) {
        float p = g_pooled[g * HID + c] * inv;
        #pragma unroll
        for (int o = 0; o < OUT_DIM; o++) l[o] = fmaf(p, fcw[c * OUT_DIM + o], l[o]);
    }
    float mx = l[0];
    #pragma unroll
    for (int o = 1; o < OUT_DIM; o++) mx = fmaxf(mx, l[o]);
    float se = 0.f;
    #pragma unroll
    for (int o = 0; o < OUT_DIM; o++) se += expf(l[o] - mx);
    float lse = mx + logf(se);
    #pragma unroll
    for (int o = 0; o < OUT_DIM; o++) out[g * OUT_DIM + o] = l[o] - lse;
}

// ---------------- launch ----------------
extern "C" void kernel_launch(void* const* d_in, const int* in_sizes, int n_in,
                              void* d_out, int out_size) {
    const float* x    = (const float*)d_in[0];
    const int*   ei   = (const int*)  d_in[1];   // width detected on device
    const int*   bat  = (const int*)  d_in[2];
    const float* W1   = (const float*)d_in[3];
    const float* as1  = (const float*)d_in[4];
    const float* ad1  = (const float*)d_in[5];
    const float* b1   = (const float*)d_in[6];
    const float* W2   = (const float*)d_in[7];
    const float* as2  = (const float*)d_in[8];
    const float* ad2  = (const float*)d_in[9];
    const float* b2   = (const float*)d_in[10];
    const float* fcw  = (const float*)d_in[11];
    const float* fcb  = (const float*)d_in[12];
    float* out = (float*)d_out;

    int N    = in_sizes[0] / IN_DIM;
    int E    = in_sizes[1] / 2;
    int Etot = E + N;
    int nh   = N * HEADS;

    const int TB = 256;
    dim3 gemm_grid(FTOT / 64, (N + 127) / 128);

    convert_edges_kernel<<<(2 * E + TB - 1) / TB, TB>>>(ei, 2 * E);
    convert_batch_kernel<<<(N + TB - 1) / TB, TB>>>(bat, N);

    // ---- layer 1 ----
    zero_acc_kernel  <<<(N * FTOT / 4 + TB - 1) / TB, TB>>>(N * FTOT / 4);
    zero_small_kernel<<<(nh + TB - 1) / TB, TB>>>(nh);
    gemm_kernel      <<<gemm_grid, TB>>>(x, W1, N, 0);
    alphas_kernel    <<<(nh * 32 + TB - 1) / TB, TB>>>(as1, ad1, N, 0);
    edge_logits_kernel<<<(Etot * HEADS + TB - 1) / TB, TB>>>(E, Etot);
    edge_exp_kernel  <<<(Etot * HEADS + TB - 1) / TB, TB>>>(E, Etot);
    edge_agg_kernel  <<<(Etot * 64 + TB - 1) / TB, TB>>>(E, Etot, 0);
    bias_elu_kernel  <<<(N * FTOT + TB - 1) / TB, TB>>>(b1, N * FTOT);

    // ---- layer 2 ----
    zero_acc_kernel  <<<(N * FTOT / 4 + TB - 1) / TB, TB>>>(N * FTOT / 4);
    zero_small_kernel<<<(nh + TB - 1) / TB, TB>>>(nh);
    gemm_kernel      <<<gemm_grid, TB>>>(x /*unused*/, W2, N, 1);
    alphas_kernel    <<<(nh * 32 + TB - 1) / TB, TB>>>(as2, ad2, N, 1);
    edge_logits_kernel<<<(Etot * HEADS + TB - 1) / TB, TB>>>(E, Etot);
    edge_exp_kernel  <<<(Etot * HEADS + TB - 1) / TB, TB>>>(E, Etot);
    edge_agg_kernel  <<<(Etot * 64 + TB - 1) / TB, TB>>>(E, Etot, 1);

    // ---- readout ----
    head_pool_kernel <<<(N * HID + TB - 1) / TB, TB>>>(b2, N);
    final_kernel     <<<1, 64>>>(fcw, fcb, out);
}

// round 2
// speedup vs baseline: 1.9493x; 1.9493x over previous
#include <cuda_runtime.h>
#include <math.h>

#define IN_DIM  256
#define HID     64
#define HEADS   4
#define FTOT    256
#define OUT_DIM 10
#define NGRAPH  64
#define MAXN    50000
#define MAXE    800000
#define CHUNK   1024

// ---------------- static scratch ----------------
__device__ float g_feat[MAXN * FTOT];      // GEMM outputs (h of current layer)
__device__ float g_lin [MAXN * FTOT];      // layer-1 activated output
__device__ float g_as  [MAXN * HEADS];
__device__ float g_ad  [MAXN * HEADS];
__device__ int   g_srcdst[2 * MAXE];
__device__ int   g_batch [MAXN];
__device__ int   g_deg   [MAXN];
__device__ int   g_rowptr[MAXN + 1];
__device__ int   g_cursor[MAXN];
__device__ int   g_esrc  [MAXE + MAXN];
__device__ int   g_partial[256];
__device__ float g_pooled[NGRAPH * HID];
__device__ float g_cnt   [NGRAPH];

// ---------------- helpers ----------------
__device__ __forceinline__ float lrelu(float v) { return v > 0.f ? v : 0.2f * v; }
__device__ __forceinline__ float elu1(float x)  { return x > 0.f ? x : expm1f(x); }

__device__ __forceinline__ unsigned f2tf(float x) {
    unsigned r;
    asm("cvt.rna.tf32.f32 %0, %1;" : "=r"(r) : "f"(x));
    return r;
}
__device__ __forceinline__ void mma_tf32(float* c, const unsigned* a, const unsigned* b) {
    asm volatile(
        "mma.sync.aligned.m16n8k8.row.col.f32.tf32.tf32.f32 "
        "{%0,%1,%2,%3},{%4,%5,%6,%7},{%8,%9},{%0,%1,%2,%3};"
        : "+f"(c[0]), "+f"(c[1]), "+f"(c[2]), "+f"(c[3])
        : "r"(a[0]), "r"(a[1]), "r"(a[2]), "r"(a[3]), "r"(b[0]), "r"(b[1]));
}
__device__ __forceinline__ void cp16(void* dst, const void* src, bool pred) {
    unsigned d = (unsigned)__cvta_generic_to_shared(dst);
    int sz = pred ? 16 : 0;
    asm volatile("cp.async.cg.shared.global [%0], [%1], 16, %2;"
                 :: "r"(d), "l"(src), "r"(sz));
}
__device__ __forceinline__ void cp_commit() { asm volatile("cp.async.commit_group;"); }
template <int W> __device__ __forceinline__ void cp_wait() {
    asm volatile("cp.async.wait_group %0;" :: "n"(W));
}

// ---------------- dtype-normalizing converters ----------------
__global__ void convert_edges_kernel(const int* __restrict__ raw, int count) {
    int nz = (raw[2 * threadIdx.x + 1] != 0);
    int any = __syncthreads_or(nz);
    int is64 = !any;
    for (int v = blockIdx.x * blockDim.x + threadIdx.x; v < count;
         v += gridDim.x * blockDim.x)
        g_srcdst[v] = is64 ? raw[2 * v] : raw[v];
}
__global__ void convert_batch_kernel(const int* __restrict__ raw, int count) {
    int base = count / 2;
    int w = (base | 1) + 2 * threadIdx.x;
    int nz = (raw[w] != 0);
    int any = __syncthreads_or(nz);
    int is64 = !any;
    for (int v = blockIdx.x * blockDim.x + threadIdx.x; v < count;
         v += gridDim.x * blockDim.x)
        g_batch[v] = is64 ? raw[2 * v] : raw[v];
}

// ---------------- CSR build ----------------
__global__ void init_kernel(int N) {
    int i = blockIdx.x * blockDim.x + threadIdx.x;
    if (i < N) g_deg[i] = 1;                     // self-loop pre-counted
    if (i < NGRAPH * HID) g_pooled[i] = 0.f;
    if (i < NGRAPH) g_cnt[i] = 0.f;
}
__global__ void count_kernel(int E) {
    int e = blockIdx.x * blockDim.x + threadIdx.x;
    if (e < E) atomicAdd(&g_deg[g_srcdst[E + e]], 1);
}
__global__ void scan1_kernel(int N) {
    __shared__ int s[256];
    int i = blockIdx.x * 256 + threadIdx.x;
    s[threadIdx.x] = (i < N) ? g_deg[i] : 0;
    __syncthreads();
    for (int off = 128; off; off >>= 1) {
        if (threadIdx.x < off) s[threadIdx.x] += s[threadIdx.x + off];
        __syncthreads();
    }
    if (!threadIdx.x) g_partial[blockIdx.x] = s[0];
}
__global__ void scan2_kernel(int nb) {
    __shared__ int s[256];
    int t = threadIdx.x;
    int v = (t < nb) ? g_partial[t] : 0;
    s[t] = v;
    __syncthreads();
    for (int off = 1; off < 256; off <<= 1) {
        int x = (t >= off) ? s[t - off] : 0;
        __syncthreads();
        s[t] += x;
        __syncthreads();
    }
    if (t < nb) g_partial[t] = s[t] - v;        // exclusive
}
__global__ void scan3_kernel(int N, int Etot) {
    __shared__ int s[256];
    int t = threadIdx.x;
    int i = blockIdx.x * 256 + t;
    int v = (i < N) ? g_deg[i] : 0;
    s[t] = v;
    __syncthreads();
    for (int off = 1; off < 256; off <<= 1) {
        int x = (t >= off) ? s[t - off] : 0;
        __syncthreads();
        s[t] += x;
        __syncthreads();
    }
    int excl = s[t] - v + g_partial[blockIdx.x];
    if (i < N) { g_rowptr[i] = excl; g_cursor[i] = excl; }
    if (i == 0) g_rowptr[N] = Etot;
}
__global__ void fill_kernel(int E, int Etot) {
    int e = blockIdx.x * blockDim.x + threadIdx.x;
    if (e >= Etot) return;
    int s, d;
    if (e < E) { s = g_srcdst[e]; d = g_srcdst[E + e]; }
    else       { s = d = e - E; }
    int pos = atomicAdd(&g_cursor[d], 1);
    g_esrc[pos] = s;
}

// ---------------- TF32 tensor-core GEMM: C[M,256] = A[M,256] @ B[256,256] ----------------
#define APAD 20
#define BPAD 136
__global__ __launch_bounds__(256, 2) void gemm_tf32_kernel(
    const float* __restrict__ Aext, const float* __restrict__ B, int M, int which)
{
    const float* __restrict__ A = which ? g_lin : Aext;
    float* __restrict__ C = g_feat;

    __shared__ float As[2][128][APAD];
    __shared__ float Bs[2][16][BPAD];

    int t = threadIdx.x;
    int lane = t & 31;
    int wid = t >> 5;
    int wm = (wid & 1) * 64;
    int wn = (wid >> 1) * 32;
    int m0 = blockIdx.y * 128;
    int n0 = blockIdx.x * 128;
    int gid = lane >> 2, tig = lane & 3;

    float cacc[4][4][4];
    #pragma unroll
    for (int a = 0; a < 4; a++)
        #pragma unroll
        for (int b = 0; b < 4; b++)
            #pragma unroll
            for (int k = 0; k < 4; k++) cacc[a][b][k] = 0.f;

#define LOAD_TILES(stage, k0)                                                   \
    {                                                                           \
        _Pragma("unroll")                                                       \
        for (int r = 0; r < 2; r++) {                                           \
            int cA = t + r * 256;                                               \
            int am = cA >> 2, ak = (cA & 3) * 4;                                \
            cp16(&As[stage][am][ak],                                            \
                 &A[(size_t)(m0 + am) * 256 + (k0) + ak], (m0 + am) < M);       \
            int bk = cA >> 5, bn = (cA & 31) * 4;                               \
            cp16(&Bs[stage][bk][bn], &B[((k0) + bk) * 256 + n0 + bn], true);    \
        }                                                                       \
        cp_commit();                                                            \
    }

    LOAD_TILES(0, 0);
    for (int kt = 0; kt < 16; kt++) {
        int s = kt & 1;
        if (kt < 15) { LOAD_TILES(s ^ 1, (kt + 1) * 16); cp_wait<1>(); }
        else         { cp_wait<0>(); }
        __syncthreads();

        #pragma unroll
        for (int k8 = 0; k8 < 2; k8++) {
            int kk = k8 * 8;
            unsigned af[4][4], bf[4][2];
            #pragma unroll
            for (int mt = 0; mt < 4; mt++) {
                int row = wm + mt * 16 + gid;
                af[mt][0] = f2tf(As[s][row][kk + tig]);
                af[mt][1] = f2tf(As[s][row + 8][kk + tig]);
                af[mt][2] = f2tf(As[s][row][kk + tig + 4]);
                af[mt][3] = f2tf(As[s][row + 8][kk + tig + 4]);
            }
            #pragma unroll
            for (int nt = 0; nt < 4; nt++) {
                int col = wn + nt * 8 + gid;
                bf[nt][0] = f2tf(Bs[s][kk + tig][col]);
                bf[nt][1] = f2tf(Bs[s][kk + tig + 4][col]);
            }
            #pragma unroll
            for (int mt = 0; mt < 4; mt++)
                #pragma unroll
                for (int nt = 0; nt < 4; nt++)
                    mma_tf32(cacc[mt][nt], af[mt], bf[nt]);
        }
        __syncthreads();
    }
#undef LOAD_TILES

    #pragma unroll
    for (int mt = 0; mt < 4; mt++) {
        int row = m0 + wm + mt * 16 + gid;
        #pragma unroll
        for (int nt = 0; nt < 4; nt++) {
            int col = n0 + wn + nt * 8 + tig * 2;
            if (row < M)
                *reinterpret_cast<float2*>(&C[(size_t)row * 256 + col]) =
                    make_float2(cacc[mt][nt][0], cacc[mt][nt][1]);
            if (row + 8 < M)
                *reinterpret_cast<float2*>(&C[(size_t)(row + 8) * 256 + col]) =
                    make_float2(cacc[mt][nt][2], cacc[mt][nt][3]);
        }
    }
}

// ---------------- per-node attention coefficients (reads g_feat) ----------------
__global__ __launch_bounds__(256) void alphas_kernel(
    const float* __restrict__ att_s, const float* __restrict__ att_d, int N)
{
    int w = (blockIdx.x * blockDim.x + threadIdx.x) >> 5;
    int lane = threadIdx.x & 31;
    if (w >= N * HEADS) return;
    int n = w >> 2, hh = w & 3;
    const float* row = g_feat + (size_t)n * FTOT + hh * HID;
    const float* sv = att_s + hh * HID;
    const float* dv = att_d + hh * HID;
    float s = row[lane] * sv[lane] + row[lane + 32] * sv[lane + 32];
    float d = row[lane] * dv[lane] + row[lane + 32] * dv[lane + 32];
    #pragma unroll
    for (int o = 16; o; o >>= 1) {
        s += __shfl_down_sync(0xFFFFFFFFu, s, o);
        d += __shfl_down_sync(0xFFFFFFFFu, d, o);
    }
    if (lane == 0) { g_as[w] = s; g_ad[w] = d; }
}

// ---------------- fused per-node GAT: softmax + gather-aggregate + epilogue ----------------
__global__ __launch_bounds__(64) void gat_node_kernel(const float* __restrict__ bias, int which)
{
    __shared__ int   s_src[CHUNK];
    __shared__ float s_m[4], s_inv[4];
    __shared__ float s_acc[FTOT];

    const float* __restrict__ h = g_feat;
    int n = blockIdx.x;
    int t = threadIdx.x;
    int lane = t & 31;
    int beg = g_rowptr[n], end = g_rowptr[n + 1];
    int deg = end - beg;
    bool multi = deg > CHUNK;
    float4 adv = *reinterpret_cast<const float4*>(&g_ad[n * 4]);

    // ---- pass 1: per-head max over edges ----
    float4 mx = make_float4(-1e30f, -1e30f, -1e30f, -1e30f);
    for (int c0 = beg; c0 < end; c0 += CHUNK) {
        int cnt = min(CHUNK, end - c0);
        for (int i = t; i < cnt; i += 64) s_src[i] = g_esrc[c0 + i];
        __syncthreads();
        if (t < 32) {
            for (int i = lane; i < cnt; i += 32) {
                int s = s_src[i];
                float4 a = *reinterpret_cast<const float4*>(&g_as[s * 4]);
                mx.x = fmaxf(mx.x, lrelu(a.x + adv.x));
                mx.y = fmaxf(mx.y, lrelu(a.y + adv.y));
                mx.z = fmaxf(mx.z, lrelu(a.z + adv.z));
                mx.w = fmaxf(mx.w, lrelu(a.w + adv.w));
            }
        }
        __syncthreads();
    }
    if (t < 32) {
        #pragma unroll
        for (int o = 16; o; o >>= 1) {
            mx.x = fmaxf(mx.x, __shfl_xor_sync(0xFFFFFFFFu, mx.x, o));
            mx.y = fmaxf(mx.y, __shfl_xor_sync(0xFFFFFFFFu, mx.y, o));
            mx.z = fmaxf(mx.z, __shfl_xor_sync(0xFFFFFFFFu, mx.z, o));
            mx.w = fmaxf(mx.w, __shfl_xor_sync(0xFFFFFFFFu, mx.w, o));
        }
    }

    // ---- pass 2: per-head sum of exp(e - max) ----
    float4 den = make_float4(0.f, 0.f, 0.f, 0.f);
    for (int c0 = beg; c0 < end; c0 += CHUNK) {
        int cnt = min(CHUNK, end - c0);
        if (multi) {
            for (int i = t; i < cnt; i += 64) s_src[i] = g_esrc[c0 + i];
            __syncthreads();
        }
        if (t < 32) {
            for (int i = lane; i < cnt; i += 32) {
                int s = s_src[i];
                float4 a = *reinterpret_cast<const float4*>(&g_as[s * 4]);
                den.x += expf(lrelu(a.x + adv.x) - mx.x);
                den.y += expf(lrelu(a.y + adv.y) - mx.y);
                den.z += expf(lrelu(a.z + adv.z) - mx.z);
                den.w += expf(lrelu(a.w + adv.w) - mx.w);
            }
        }
        if (multi) __syncthreads();
    }
    if (t < 32) {
        #pragma unroll
        for (int o = 16; o; o >>= 1) {
            den.x += __shfl_xor_sync(0xFFFFFFFFu, den.x, o);
            den.y += __shfl_xor_sync(0xFFFFFFFFu, den.y, o);
            den.z += __shfl_xor_sync(0xFFFFFFFFu, den.z, o);
            den.w += __shfl_xor_sync(0xFFFFFFFFu, den.w, o);
        }
        if (lane == 0) {
            s_m[0] = mx.x; s_m[1] = mx.y; s_m[2] = mx.z; s_m[3] = mx.w;
            s_inv[0] = 1.f / (den.x + 1e-16f);
            s_inv[1] = 1.f / (den.y + 1e-16f);
            s_inv[2] = 1.f / (den.z + 1e-16f);
            s_inv[3] = 1.f / (den.w + 1e-16f);
        }
    }
    __syncthreads();

    // ---- pass 3: weighted gather-aggregate (thread owns float4 slot t) ----
    int hh = t >> 4;
    float m_h = s_m[hh], inv_h = s_inv[hh];
    float ad_h = (hh & 2) ? ((hh & 1) ? adv.w : adv.z) : ((hh & 1) ? adv.y : adv.x);
    float4 acc = make_float4(0.f, 0.f, 0.f, 0.f);

    for (int c0 = beg; c0 < end; c0 += CHUNK) {
        int cnt = min(CHUNK, end - c0);
        if (multi) {
            __syncthreads();
            for (int i = t; i < cnt; i += 64) s_src[i] = g_esrc[c0 + i];
            __syncthreads();
        }
        int i = 0;
        for (; i + 4 <= cnt; i += 4) {
            int s0 = s_src[i], s1 = s_src[i + 1], s2 = s_src[i + 2], s3 = s_src[i + 3];
            float4 h0 = *reinterpret_cast<const float4*>(&h[(size_t)s0 * FTOT + t * 4]);
            float4 h1 = *reinterpret_cast<const float4*>(&h[(size_t)s1 * FTOT + t * 4]);
            float4 h2 = *reinterpret_cast<const float4*>(&h[(size_t)s2 * FTOT + t * 4]);
            float4 h3 = *reinterpret_cast<const float4*>(&h[(size_t)s3 * FTOT + t * 4]);
            float a0 = expf(lrelu(g_as[s0 * 4 + hh] + ad_h) - m_h) * inv_h;
            float a1 = expf(lrelu(g_as[s1 * 4 + hh] + ad_h) - m_h) * inv_h;
            float a2 = expf(lrelu(g_as[s2 * 4 + hh] + ad_h) - m_h) * inv_h;
            float a3 = expf(lrelu(g_as[s3 * 4 + hh] + ad_h) - m_h) * inv_h;
            acc.x += h0.x * a0 + h1.x * a1 + h2.x * a2 + h3.x * a3;
            acc.y += h0.y * a0 + h1.y * a1 + h2.y * a2 + h3.y * a3;
            acc.z += h0.z * a0 + h1.z * a1 + h2.z * a2 + h3.z * a3;
            acc.w += h0.w * a0 + h1.w * a1 + h2.w * a2 + h3.w * a3;
        }
        for (; i < cnt; i++) {
            int s0 = s_src[i];
            float4 h0 = *reinterpret_cast<const float4*>(&h[(size_t)s0 * FTOT + t * 4]);
            float a0 = expf(lrelu(g_as[s0 * 4 + hh] + ad_h) - m_h) * inv_h;
            acc.x += h0.x * a0; acc.y += h0.y * a0;
            acc.z += h0.z * a0; acc.w += h0.w * a0;
        }
    }

    // ---- epilogue ----
    if (which == 0) {
        float4 b = *reinterpret_cast<const float4*>(&bias[t * 4]);
        float4 o = make_float4(elu1(acc.x + b.x), elu1(acc.y + b.y),
                               elu1(acc.z + b.z), elu1(acc.w + b.w));
        *reinterpret_cast<float4*>(&g_lin[(size_t)n * FTOT + t * 4]) = o;
    } else {
        *reinterpret_cast<float4*>(&s_acc[t * 4]) = acc;
        __syncthreads();
        if (t < 16) {
            float4 v0 = *reinterpret_cast<const float4*>(&s_acc[t * 4]);
            float4 v1 = *reinterpret_cast<const float4*>(&s_acc[t * 4 + 64]);
            float4 v2 = *reinterpret_cast<const float4*>(&s_acc[t * 4 + 128]);
            float4 v3 = *reinterpret_cast<const float4*>(&s_acc[t * 4 + 192]);
            float4 b = *reinterpret_cast<const float4*>(&bias[t * 4]);
            float o0 = elu1(0.25f * (v0.x + v1.x + v2.x + v3.x) + b.x);
            float o1 = elu1(0.25f * (v0.y + v1.y + v2.y + v3.y) + b.y);
            float o2 = elu1(0.25f * (v0.z + v1.z + v2.z + v3.z) + b.z);
            float o3 = elu1(0.25f * (v0.w + v1.w + v2.w + v3.w) + b.w);
            int g = g_batch[n];
            atomicAdd(&g_pooled[g * HID + t * 4 + 0], o0);
            atomicAdd(&g_pooled[g * HID + t * 4 + 1], o1);
            atomicAdd(&g_pooled[g * HID + t * 4 + 2], o2);
            atomicAdd(&g_pooled[g * HID + t * 4 + 3], o3);
            if (t == 0) atomicAdd(&g_cnt[g], 1.0f);
        }
    }
}

// ---------------- classifier + log_softmax ----------------
__global__ void final_kernel(const float* __restrict__ fcw, const float* __restrict__ fcb,
                             float* __restrict__ out) {
    int g = threadIdx.x;
    if (g >= NGRAPH) return;
    float inv = 1.f / fmaxf(g_cnt[g], 1.f);
    float l[OUT_DIM];
    #pragma unroll
    for (int o = 0; o < OUT_DIM; o++) l[o] = fcb[o];
    for (int c = 0; c < HID; c++) {
        float p = g_pooled[g * HID + c] * inv;
        #pragma unroll
        for (int o = 0; o < OUT_DIM; o++) l[o] = fmaf(p, fcw[c * OUT_DIM + o], l[o]);
    }
    float mx = l[0];
    #pragma unroll
    for (int o = 1; o < OUT_DIM; o++) mx = fmaxf(mx, l[o]);
    float se = 0.f;
    #pragma unroll
    for (int o = 0; o < OUT_DIM; o++) se += expf(l[o] - mx);
    float lse = mx + logf(se);
    #pragma unroll
    for (int o = 0; o < OUT_DIM; o++) out[g * OUT_DIM + o] = l[o] - lse;
}

// ---------------- launch ----------------
extern "C" void kernel_launch(void* const* d_in, const int* in_sizes, int n_in,
                              void* d_out, int out_size) {
    const float* x   = (const float*)d_in[0];
    const int*   ei  = (const int*)  d_in[1];
    const int*   bat = (const int*)  d_in[2];
    const float* W1  = (const float*)d_in[3];
    const float* as1 = (const float*)d_in[4];
    const float* ad1 = (const float*)d_in[5];
    const float* b1  = (const float*)d_in[6];
    const float* W2  = (const float*)d_in[7];
    const float* as2 = (const float*)d_in[8];
    const float* ad2 = (const float*)d_in[9];
    const float* b2  = (const float*)d_in[10];
    const float* fcw = (const float*)d_in[11];
    const float* fcb = (const float*)d_in[12];
    float* out = (float*)d_out;

    int N    = in_sizes[0] / IN_DIM;
    int E    = in_sizes[1] / 2;
    int Etot = E + N;
    int nb   = (N + 255) / 256;
    const int TB = 256;
    dim3 gemm_grid(2, (N + 127) / 128);

    convert_edges_kernel<<<(2 * E + TB - 1) / TB, TB>>>(ei, 2 * E);
    convert_batch_kernel<<<(N + TB - 1) / TB, TB>>>(bat, N);

    // CSR build (shared by both layers)
    init_kernel <<<nb, TB>>>(N);
    count_kernel<<<(E + TB - 1) / TB, TB>>>(E);
    scan1_kernel<<<nb, TB>>>(N);
    scan2_kernel<<<1, TB>>>(nb);
    scan3_kernel<<<nb, TB>>>(N, Etot);
    fill_kernel <<<(Etot + TB - 1) / TB, TB>>>(E, Etot);

    // layer 1
    gemm_tf32_kernel<<<gemm_grid, TB>>>(x, W1, N, 0);
    alphas_kernel   <<<(N * HEADS * 32 + TB - 1) / TB, TB>>>(as1, ad1, N);
    gat_node_kernel <<<N, 64>>>(b1, 0);

    // layer 2
    gemm_tf32_kernel<<<gemm_grid, TB>>>(nullptr, W2, N, 1);
    alphas_kernel   <<<(N * HEADS * 32 + TB - 1) / TB, TB>>>(as2, ad2, N);
    gat_node_kernel <<<N, 64>>>(b2, 1);

    // readout
    final_kernel<<<1, 64>>>(fcw, fcb, out);
}

// round 3
// speedup vs baseline: 2.7848x; 1.4286x over previous
#include <cuda_runtime.h>
#include <cuda_fp16.h>
#include <math.h>

#define IN_DIM  256
#define HID     64
#define HEADS   4
#define FTOT    256
#define OUT_DIM 10
#define NGRAPH  64
#define MAXN    50000
#define MAXE    800000

// ---------------- static scratch ----------------
__device__ float  g_feat  [MAXN * FTOT];     // GEMM output (fp32, current layer)
__device__ __half g_feat_h[MAXN * FTOT];     // fp16 mirror for edge gather
__device__ float  g_lin   [MAXN * FTOT];     // layer-1 activated output
__device__ float  g_as    [MAXN * HEADS];
__device__ float  g_ad    [MAXN * HEADS];
__device__ int    g_srcdst[2 * MAXE];
__device__ int    g_batch [MAXN];
__device__ int    g_deg   [MAXN];
__device__ int    g_rowptr[MAXN + 1];
__device__ int    g_cursor[MAXN];
__device__ int    g_esrc  [MAXE + MAXN];
__device__ int    g_partial[256];
__device__ float  g_pooled[NGRAPH * HID];
__device__ float  g_cnt   [NGRAPH];

// ---------------- helpers ----------------
__device__ __forceinline__ float lrelu(float v) { return v > 0.f ? v : 0.2f * v; }
__device__ __forceinline__ float elu1(float x)  { return x > 0.f ? x : expm1f(x); }
__device__ __forceinline__ float4 lrelu4(float4 a, float4 b) {
    return make_float4(lrelu(a.x + b.x), lrelu(a.y + b.y),
                       lrelu(a.z + b.z), lrelu(a.w + b.w));
}
__device__ __forceinline__ void max4(float4& m, float4 v) {
    m.x = fmaxf(m.x, v.x); m.y = fmaxf(m.y, v.y);
    m.z = fmaxf(m.z, v.z); m.w = fmaxf(m.w, v.w);
}
__device__ __forceinline__ void red_add_f4(float* addr, float4 v) {
    asm volatile("red.global.add.v4.f32 [%0], {%1, %2, %3, %4};"
                 :: "l"(addr), "f"(v.x), "f"(v.y), "f"(v.z), "f"(v.w)
                 : "memory");
}
__device__ __forceinline__ unsigned f2tf(float x) {
    unsigned r;
    asm("cvt.rna.tf32.f32 %0, %1;" : "=r"(r) : "f"(x));
    return r;
}
__device__ __forceinline__ void mma_tf32(float* c, const unsigned* a, const unsigned* b) {
    asm volatile(
        "mma.sync.aligned.m16n8k8.row.col.f32.tf32.tf32.f32 "
        "{%0,%1,%2,%3},{%4,%5,%6,%7},{%8,%9},{%0,%1,%2,%3};"
        : "+f"(c[0]), "+f"(c[1]), "+f"(c[2]), "+f"(c[3])
        : "r"(a[0]), "r"(a[1]), "r"(a[2]), "r"(a[3]), "r"(b[0]), "r"(b[1]));
}
__device__ __forceinline__ void cp16(void* dst, const void* src, bool pred) {
    unsigned d = (unsigned)__cvta_generic_to_shared(dst);
    int sz = pred ? 16 : 0;
    asm volatile("cp.async.cg.shared.global [%0], [%1], 16, %2;"
                 :: "r"(d), "l"(src), "r"(sz));
}
__device__ __forceinline__ void cp_commit() { asm volatile("cp.async.commit_group;"); }
template <int W> __device__ __forceinline__ void cp_wait() {
    asm volatile("cp.async.wait_group %0;" :: "n"(W));
}

// ---------------- dtype-normalizing converters ----------------
__global__ void convert_edges_kernel(const int* __restrict__ raw, int count) {
    int nz = (raw[2 * threadIdx.x + 1] != 0);
    int any = __syncthreads_or(nz);
    int is64 = !any;
    for (int v = blockIdx.x * blockDim.x + threadIdx.x; v < count;
         v += gridDim.x * blockDim.x)
        g_srcdst[v] = is64 ? raw[2 * v] : raw[v];
}
__global__ void convert_batch_kernel(const int* __restrict__ raw, int count) {
    int base = count / 2;
    int w = (base | 1) + 2 * threadIdx.x;
    int nz = (raw[w] != 0);
    int any = __syncthreads_or(nz);
    int is64 = !any;
    for (int v = blockIdx.x * blockDim.x + threadIdx.x; v < count;
         v += gridDim.x * blockDim.x)
        g_batch[v] = is64 ? raw[2 * v] : raw[v];
}

// ---------------- CSR build ----------------
__global__ void init_kernel(int N) {
    int i = blockIdx.x * blockDim.x + threadIdx.x;
    if (i < N) g_deg[i] = 1;
    if (i < NGRAPH * HID) g_pooled[i] = 0.f;
    if (i < NGRAPH) g_cnt[i] = 0.f;
}
__global__ void count_kernel(int E) {
    int e = blockIdx.x * blockDim.x + threadIdx.x;
    if (e < E) atomicAdd(&g_deg[g_srcdst[E + e]], 1);
}
__global__ void scan1_kernel(int N) {
    __shared__ int s[256];
    int i = blockIdx.x * 256 + threadIdx.x;
    s[threadIdx.x] = (i < N) ? g_deg[i] : 0;
    __syncthreads();
    for (int off = 128; off; off >>= 1) {
        if (threadIdx.x < off) s[threadIdx.x] += s[threadIdx.x + off];
        __syncthreads();
    }
    if (!threadIdx.x) g_partial[blockIdx.x] = s[0];
}
__global__ void scan2_kernel(int nb) {
    __shared__ int s[256];
    int t = threadIdx.x;
    int v = (t < nb) ? g_partial[t] : 0;
    s[t] = v;
    __syncthreads();
    for (int off = 1; off < 256; off <<= 1) {
        int x = (t >= off) ? s[t - off] : 0;
        __syncthreads();
        s[t] += x;
        __syncthreads();
    }
    if (t < nb) g_partial[t] = s[t] - v;
}
__global__ void scan3_kernel(int N, int Etot) {
    __shared__ int s[256];
    int t = threadIdx.x;
    int i = blockIdx.x * 256 + t;
    int v = (i < N) ? g_deg[i] : 0;
    s[t] = v;
    __syncthreads();
    for (int off = 1; off < 256; off <<= 1) {
        int x = (t >= off) ? s[t - off] : 0;
        __syncthreads();
        s[t] += x;
        __syncthreads();
    }
    int excl = s[t] - v + g_partial[blockIdx.x];
    if (i < N) { g_rowptr[i] = excl; g_cursor[i] = excl; }
    if (i == 0) g_rowptr[N] = Etot;
}
__global__ void fill_kernel(int E, int Etot) {
    int e = blockIdx.x * blockDim.x + threadIdx.x;
    if (e >= Etot) return;
    int s, d;
    if (e < E) { s = g_srcdst[e]; d = g_srcdst[E + e]; }
    else       { s = d = e - E; }
    int pos = atomicAdd(&g_cursor[d], 1);
    g_esrc[pos] = s;
}

// ---------------- TF32 tensor-core GEMM (+ fp16 mirror) ----------------
#define APAD 20
#define BPAD 136
__global__ __launch_bounds__(256, 2) void gemm_tf32_kernel(
    const float* __restrict__ Aext, const float* __restrict__ B, int M, int which)
{
    const float* __restrict__ A = which ? g_lin : Aext;
    float* __restrict__ C = g_feat;

    __shared__ float As[2][128][APAD];
    __shared__ float Bs[2][16][BPAD];

    int t = threadIdx.x;
    int lane = t & 31;
    int wid = t >> 5;
    int wm = (wid & 1) * 64;
    int wn = (wid >> 1) * 32;
    int m0 = blockIdx.y * 128;
    int n0 = blockIdx.x * 128;
    int gid = lane >> 2, tig = lane & 3;

    float cacc[4][4][4];
    #pragma unroll
    for (int a = 0; a < 4; a++)
        #pragma unroll
        for (int b = 0; b < 4; b++)
            #pragma unroll
            for (int k = 0; k < 4; k++) cacc[a][b][k] = 0.f;

#define LOAD_TILES(stage, k0)                                                   \
    {                                                                           \
        _Pragma("unroll")                                                       \
        for (int r = 0; r < 2; r++) {                                           \
            int cA = t + r * 256;                                               \
            int am = cA >> 2, ak = (cA & 3) * 4;                                \
            cp16(&As[stage][am][ak],                                            \
                 &A[(size_t)(m0 + am) * 256 + (k0) + ak], (m0 + am) < M);       \
            int bk = cA >> 5, bn = (cA & 31) * 4;                               \
            cp16(&Bs[stage][bk][bn], &B[((k0) + bk) * 256 + n0 + bn], true);    \
        }                                                                       \
        cp_commit();                                                            \
    }

    LOAD_TILES(0, 0);
    for (int kt = 0; kt < 16; kt++) {
        int s = kt & 1;
        if (kt < 15) { LOAD_TILES(s ^ 1, (kt + 1) * 16); cp_wait<1>(); }
        else         { cp_wait<0>(); }
        __syncthreads();

        #pragma unroll
        for (int k8 = 0; k8 < 2; k8++) {
            int kk = k8 * 8;
            unsigned af[4][4], bf[4][2];
            #pragma unroll
            for (int mt = 0; mt < 4; mt++) {
                int row = wm + mt * 16 + gid;
                af[mt][0] = f2tf(As[s][row][kk + tig]);
                af[mt][1] = f2tf(As[s][row + 8][kk + tig]);
                af[mt][2] = f2tf(As[s][row][kk + tig + 4]);
                af[mt][3] = f2tf(As[s][row + 8][kk + tig + 4]);
            }
            #pragma unroll
            for (int nt = 0; nt < 4; nt++) {
                int col = wn + nt * 8 + gid;
                bf[nt][0] = f2tf(Bs[s][kk + tig][col]);
                bf[nt][1] = f2tf(Bs[s][kk + tig + 4][col]);
            }
            #pragma unroll
            for (int mt = 0; mt < 4; mt++)
                #pragma unroll
                for (int nt = 0; nt < 4; nt++)
                    mma_tf32(cacc[mt][nt], af[mt], bf[nt]);
        }
        __syncthreads();
    }
#undef LOAD_TILES

    #pragma unroll
    for (int mt = 0; mt < 4; mt++) {
        int row = m0 + wm + mt * 16 + gid;
        #pragma unroll
        for (int nt = 0; nt < 4; nt++) {
            int col = n0 + wn + nt * 8 + tig * 2;
            if (row < M) {
                *reinterpret_cast<float2*>(&C[(size_t)row * 256 + col]) =
                    make_float2(cacc[mt][nt][0], cacc[mt][nt][1]);
                *reinterpret_cast<__half2*>(&g_feat_h[(size_t)row * 256 + col]) =
                    __floats2half2_rn(cacc[mt][nt][0], cacc[mt][nt][1]);
            }
            if (row + 8 < M) {
                *reinterpret_cast<float2*>(&C[(size_t)(row + 8) * 256 + col]) =
                    make_float2(cacc[mt][nt][2], cacc[mt][nt][3]);
                *reinterpret_cast<__half2*>(&g_feat_h[(size_t)(row + 8) * 256 + col]) =
                    __floats2half2_rn(cacc[mt][nt][2], cacc[mt][nt][3]);
            }
        }
    }
}

// ---------------- per-node attention coefficients ----------------
__global__ __launch_bounds__(256) void alphas_kernel(
    const float* __restrict__ att_s, const float* __restrict__ att_d, int N)
{
    int w = (blockIdx.x * blockDim.x + threadIdx.x) >> 5;
    int lane = threadIdx.x & 31;
    if (w >= N * HEADS) return;
    int n = w >> 2, hh = w & 3;
    const float* row = g_feat + (size_t)n * FTOT + hh * HID;
    const float* sv = att_s + hh * HID;
    const float* dv = att_d + hh * HID;
    float s = row[lane] * sv[lane] + row[lane + 32] * sv[lane + 32];
    float d = row[lane] * dv[lane] + row[lane + 32] * dv[lane + 32];
    #pragma unroll
    for (int o = 16; o; o >>= 1) {
        s += __shfl_down_sync(0xFFFFFFFFu, s, o);
        d += __shfl_down_sync(0xFFFFFFFFu, d, o);
    }
    if (lane == 0) { g_as[w] = s; g_ad[w] = d; }
}

// ---------------- warp-per-node GAT: softmax + fp16 gather + epilogue ----------------
__global__ __launch_bounds__(256) void gat_warp_kernel(const float* __restrict__ bias, int which)
{
    __shared__ int   s_src  [8][64];
    __shared__ float s_alpha[8][64][4];

    int w    = threadIdx.x >> 5;
    int lane = threadIdx.x & 31;
    int n    = blockIdx.x * 8 + w;
    if (n >= gridDim.y * 0 + (int)0x7FFFFFFF) {} // no-op (keeps signature simple)
    int N_total = gridDim.x * 8;                  // upper bound; real guard below
    (void)N_total;
    // actual node count passed via bias? no — guard with rowptr trick:
    // we launch exactly ceil(N/8) blocks and pass N via constant below.
    extern __shared__ int _dummy[];               // unused

    int beg, end;
    // N is stored in g_partial[255] by scan2 caller? simpler: guard via gridDim:
    // host guarantees n < N check using g_rowptr only valid if n < N.
    // We pass N through blockIdx trick: host sets grid.y = 1; we need explicit N.
    // (N passed as kernel arg below)
    beg = 0; end = 0; // overwritten
    // --- real body in gat_warp_body ---
    // (see parameterized version)
    // This stub is never used.
    if (true) return;
    (void)beg; (void)end; (void)lane; (void)bias; (void)which;
    (void)s_src; (void)s_alpha;
}

__global__ __launch_bounds__(256) void gat_warp(const float* __restrict__ bias,
                                                int N, int which)
{
    __shared__ int   s_src  [8][64];
    __shared__ float s_alpha[8][64][4];

    int w    = threadIdx.x >> 5;
    int lane = threadIdx.x & 31;
    int n    = blockIdx.x * 8 + w;
    if (n >= N) return;

    int beg = g_rowptr[n], end = g_rowptr[n + 1];
    int deg = end - beg;
    float4 adv = *reinterpret_cast<const float4*>(&g_ad[n * 4]);
    int hh = lane >> 3;                       // head owning this lane's 8 features

    float4 m4  = make_float4(-1e30f, -1e30f, -1e30f, -1e30f);
    float4 den = make_float4(0.f, 0.f, 0.f, 0.f);

    if (deg <= 64) {
        // ---- fast path: edge logits in registers ----
        int s0 = (lane      < deg) ? g_esrc[beg + lane]      : -1;
        int s1 = (lane + 32 < deg) ? g_esrc[beg + lane + 32] : -1;
        if (lane < deg)      s_src[w][lane]      = s0;
        if (lane + 32 < deg) s_src[w][lane + 32] = s1;
        float4 v0 = make_float4(-1e30f, -1e30f, -1e30f, -1e30f), v1 = v0;
        if (s0 >= 0) v0 = lrelu4(*reinterpret_cast<const float4*>(&g_as[s0 * 4]), adv);
        if (s1 >= 0) v1 = lrelu4(*reinterpret_cast<const float4*>(&g_as[s1 * 4]), adv);
        m4 = v0; max4(m4, v1);
        #pragma unroll
        for (int o = 16; o; o >>= 1) {
            m4.x = fmaxf(m4.x, __shfl_xor_sync(0xFFFFFFFFu, m4.x, o));
            m4.y = fmaxf(m4.y, __shfl_xor_sync(0xFFFFFFFFu, m4.y, o));
            m4.z = fmaxf(m4.z, __shfl_xor_sync(0xFFFFFFFFu, m4.z, o));
            m4.w = fmaxf(m4.w, __shfl_xor_sync(0xFFFFFFFFu, m4.w, o));
        }
        float4 e0 = make_float4(0.f, 0.f, 0.f, 0.f), e1 = e0;
        if (s0 >= 0) e0 = make_float4(expf(v0.x - m4.x), expf(v0.y - m4.y),
                                      expf(v0.z - m4.z), expf(v0.w - m4.w));
        if (s1 >= 0) e1 = make_float4(expf(v1.x - m4.x), expf(v1.y - m4.y),
                                      expf(v1.z - m4.z), expf(v1.w - m4.w));
        den = make_float4(e0.x + e1.x, e0.y + e1.y, e0.z + e1.z, e0.w + e1.w);
        #pragma unroll
        for (int o = 16; o; o >>= 1) {
            den.x += __shfl_xor_sync(0xFFFFFFFFu, den.x, o);
            den.y += __shfl_xor_sync(0xFFFFFFFFu, den.y, o);
            den.z += __shfl_xor_sync(0xFFFFFFFFu, den.z, o);
            den.w += __shfl_xor_sync(0xFFFFFFFFu, den.w, o);
        }
        float4 inv = make_float4(1.f / (den.x + 1e-16f), 1.f / (den.y + 1e-16f),
                                 1.f / (den.z + 1e-16f), 1.f / (den.w + 1e-16f));
        if (s0 >= 0)
            *reinterpret_cast<float4*>(&s_alpha[w][lane][0]) =
                make_float4(e0.x * inv.x, e0.y * inv.y, e0.z * inv.z, e0.w * inv.w);
        if (s1 >= 0)
            *reinterpret_cast<float4*>(&s_alpha[w][lane + 32][0]) =
                make_float4(e1.x * inv.x, e1.y * inv.y, e1.z * inv.z, e1.w * inv.w);
        __syncwarp();

        // ---- aggregation: lane owns 8 features, fp16 gather ----
        float acc[8] = {0.f, 0.f, 0.f, 0.f, 0.f, 0.f, 0.f, 0.f};
        const __half* __restrict__ H = g_feat_h;
        int j = 0;
        for (; j + 4 <= deg; j += 4) {
            int t0 = s_src[w][j], t1 = s_src[w][j + 1];
            int t2 = s_src[w][j + 2], t3 = s_src[w][j + 3];
            float a0 = s_alpha[w][j][hh],     a1 = s_alpha[w][j + 1][hh];
            float a2 = s_alpha[w][j + 2][hh], a3 = s_alpha[w][j + 3][hh];
            uint4 q0 = *reinterpret_cast<const uint4*>(&H[(size_t)t0 * FTOT + lane * 8]);
            uint4 q1 = *reinterpret_cast<const uint4*>(&H[(size_t)t1 * FTOT + lane * 8]);
            uint4 q2 = *reinterpret_cast<const uint4*>(&H[(size_t)t2 * FTOT + lane * 8]);
            uint4 q3 = *reinterpret_cast<const uint4*>(&H[(size_t)t3 * FTOT + lane * 8]);
            #pragma unroll
            for (int p = 0; p < 4; p++) {
                float2 f0 = __half22float2(*(reinterpret_cast<const __half2*>(&q0) + p));
                float2 f1 = __half22float2(*(reinterpret_cast<const __half2*>(&q1) + p));
                float2 f2 = __half22float2(*(reinterpret_cast<const __half2*>(&q2) + p));
                float2 f3 = __half22float2(*(reinterpret_cast<const __half2*>(&q3) + p));
                acc[2*p]   += a0 * f0.x + a1 * f1.x + a2 * f2.x + a3 * f3.x;
                acc[2*p+1] += a0 * f0.y + a1 * f1.y + a2 * f2.y + a3 * f3.y;
            }
        }
        for (; j < deg; j++) {
            int t0 = s_src[w][j];
            float a0 = s_alpha[w][j][hh];
            uint4 q0 = *reinterpret_cast<const uint4*>(&H[(size_t)t0 * FTOT + lane * 8]);
            #pragma unroll
            for (int p = 0; p < 4; p++) {
                float2 f0 = __half22float2(*(reinterpret_cast<const __half2*>(&q0) + p));
                acc[2*p]   += a0 * f0.x;
                acc[2*p+1] += a0 * f0.y;
            }
        }

        // ---- epilogue ----
        if (which == 0) {
            float b[8];
            *reinterpret_cast<float4*>(&b[0]) =
                *reinterpret_cast<const float4*>(&bias[lane * 8]);
            *reinterpret_cast<float4*>(&b[4]) =
                *reinterpret_cast<const float4*>(&bias[lane * 8 + 4]);
            float o[8];
            #pragma unroll
            for (int p = 0; p < 8; p++) o[p] = elu1(acc[p] + b[p]);
            *reinterpret_cast<float4*>(&g_lin[(size_t)n * FTOT + lane * 8]) =
                *reinterpret_cast<const float4*>(&o[0]);
            *reinterpret_cast<float4*>(&g_lin[(size_t)n * FTOT + lane * 8 + 4]) =
                *reinterpret_cast<const float4*>(&o[4]);
        } else {
            #pragma unroll
            for (int p = 0; p < 8; p++) {
                acc[p] += __shfl_xor_sync(0xFFFFFFFFu, acc[p], 8);
                acc[p] += __shfl_xor_sync(0xFFFFFFFFu, acc[p], 16);
            }
            if (lane < 8) {
                int g = g_batch[n];
                float o[8];
                #pragma unroll
                for (int p = 0; p < 8; p++)
                    o[p] = elu1(0.25f * acc[p] + bias[lane * 8 + p]);
                red_add_f4(&g_pooled[g * HID + lane * 8],
                           make_float4(o[0], o[1], o[2], o[3]));
                red_add_f4(&g_pooled[g * HID + lane * 8 + 4],
                           make_float4(o[4], o[5], o[6], o[7]));
                if (lane == 0) atomicAdd(&g_cnt[g], 1.0f);
            }
        }
        return;
    }

    // ---- general path (deg > 64, rare) ----
    for (int c0 = beg; c0 < end; c0 += 64) {
        int cnt = min(64, end - c0);
        int s0 = (lane < cnt) ? g_esrc[c0 + lane] : -1;
        int s1 = (lane + 32 < cnt) ? g_esrc[c0 + lane + 32] : -1;
        if (s0 >= 0) max4(m4, lrelu4(*reinterpret_cast<const float4*>(&g_as[s0 * 4]), adv));
        if (s1 >= 0) max4(m4, lrelu4(*reinterpret_cast<const float4*>(&g_as[s1 * 4]), adv));
    }
    #pragma unroll
    for (int o = 16; o; o >>= 1) {
        m4.x = fmaxf(m4.x, __shfl_xor_sync(0xFFFFFFFFu, m4.x, o));
        m4.y = fmaxf(m4.y, __shfl_xor_sync(0xFFFFFFFFu, m4.y, o));
        m4.z = fmaxf(m4.z, __shfl_xor_sync(0xFFFFFFFFu, m4.z, o));
        m4.w = fmaxf(m4.w, __shfl_xor_sync(0xFFFFFFFFu, m4.w, o));
    }
    for (int c0 = beg; c0 < end; c0 += 64) {
        int cnt = min(64, end - c0);
        int s0 = (lane < cnt) ? g_esrc[c0 + lane] : -1;
        int s1 = (lane + 32 < cnt) ? g_esrc[c0 + lane + 32] : -1;
        if (s0 >= 0) {
            float4 v = lrelu4(*reinterpret_cast<const float4*>(&g_as[s0 * 4]), adv);
            den.x += expf(v.x - m4.x); den.y += expf(v.y - m4.y);
            den.z += expf(v.z - m4.z); den.w += expf(v.w - m4.w);
        }
        if (s1 >= 0) {
            float4 v = lrelu4(*reinterpret_cast<const float4*>(&g_as[s1 * 4]), adv);
            den.x += expf(v.x - m4.x); den.y += expf(v.y - m4.y);
            den.z += expf(v.z - m4.z); den.w += expf(v.w - m4.w);
        }
    }
    #pragma unroll
    for (int o = 16; o; o >>= 1) {
        den.x += __shfl_xor_sync(0xFFFFFFFFu, den.x, o);
        den.y += __shfl_xor_sync(0xFFFFFFFFu, den.y, o);
        den.z += __shfl_xor_sync(0xFFFFFFFFu, den.z, o);
        den.w += __shfl_xor_sync(0xFFFFFFFFu, den.w, o);
    }
    float4 inv = make_float4(1.f / (den.x + 1e-16f), 1.f / (den.y + 1e-16f),
                             1.f / (den.z + 1e-16f), 1.f / (den.w + 1e-16f));

    float acc[8] = {0.f, 0.f, 0.f, 0.f, 0.f, 0.f, 0.f, 0.f};
    const __half* __restrict__ H = g_feat_h;
    for (int c0 = beg; c0 < end; c0 += 64) {
        int cnt = min(64, end - c0);
        __syncwarp();
        #pragma unroll
        for (int r = 0; r < 2; r++) {
            int i = lane + r * 32;
            if (i < cnt) {
                int s = g_esrc[c0 + i];
                s_src[w][i] = s;
                float4 v = lrelu4(*reinterpret_cast<const float4*>(&g_as[s * 4]), adv);
                *reinterpret_cast<float4*>(&s_alpha[w][i][0]) =
                    make_float4(expf(v.x - m4.x) * inv.x, expf(v.y - m4.y) * inv.y,
                                expf(v.z - m4.z) * inv.z, expf(v.w - m4.w) * inv.w);
            }
        }
        __syncwarp();
        for (int j = 0; j < cnt; j++) {
            int s = s_src[w][j];
            float a = s_alpha[w][j][hh];
            uint4 q = *reinterpret_cast<const uint4*>(&H[(size_t)s * FTOT + lane * 8]);
            #pragma unroll
            for (int p = 0; p < 4; p++) {
                float2 f = __half22float2(*(reinterpret_cast<const __half2*>(&q) + p));
                acc[2*p]   += a * f.x;
                acc[2*p+1] += a * f.y;
            }
        }
    }

    if (which == 0) {
        float o[8];
        #pragma unroll
        for (int p = 0; p < 8; p++) o[p] = elu1(acc[p] + bias[lane * 8 + p]);
        *reinterpret_cast<float4*>(&g_lin[(size_t)n * FTOT + lane * 8]) =
            *reinterpret_cast<const float4*>(&o[0]);
        *reinterpret_cast<float4*>(&g_lin[(size_t)n * FTOT + lane * 8 + 4]) =
            *reinterpret_cast<const float4*>(&o[4]);
    } else {
        #pragma unroll
        for (int p = 0; p < 8; p++) {
            acc[p] += __shfl_xor_sync(0xFFFFFFFFu, acc[p], 8);
            acc[p] += __shfl_xor_sync(0xFFFFFFFFu, acc[p], 16);
        }
        if (lane < 8) {
            int g = g_batch[n];
            float o[8];
            #pragma unroll
            for (int p = 0; p < 8; p++)
                o[p] = elu1(0.25f * acc[p] + bias[lane * 8 + p]);
            red_add_f4(&g_pooled[g * HID + lane * 8],
                       make_float4(o[0], o[1], o[2], o[3]));
            red_add_f4(&g_pooled[g * HID + lane * 8 + 4],
                       make_float4(o[4], o[5], o[6], o[7]));
            if (lane == 0) atomicAdd(&g_cnt[g], 1.0f);
        }
    }
}

// ---------------- classifier + log_softmax ----------------
__global__ void final_kernel(const float* __restrict__ fcw, const float* __restrict__ fcb,
                             float* __restrict__ out) {
    int g = threadIdx.x;
    if (g >= NGRAPH) return;
    float inv = 1.f / fmaxf(g_cnt[g], 1.f);
    float l[OUT_DIM];
    #pragma unroll
    for (int o = 0; o < OUT_DIM; o++) l[o] = fcb[o];
    for (int c = 0; c < HID; c++) {
        float p = g_pooled[g * HID + c] * inv;
        #pragma unroll
        for (int o = 0; o < OUT_DIM; o++) l[o] = fmaf(p, fcw[c * OUT_DIM + o], l[o]);
    }
    float mx = l[0];
    #pragma unroll
    for (int o = 1; o < OUT_DIM; o++) mx = fmaxf(mx, l[o]);
    float se = 0.f;
    #pragma unroll
    for (int o = 0; o < OUT_DIM; o++) se += expf(l[o] - mx);
    float lse = mx + logf(se);
    #pragma unroll
    for (int o = 0; o < OUT_DIM; o++) out[g * OUT_DIM + o] = l[o] - lse;
}

// ---------------- launch ----------------
extern "C" void kernel_launch(void* const* d_in, const int* in_sizes, int n_in,
                              void* d_out, int out_size) {
    const float* x   = (const float*)d_in[0];
    const int*   ei  = (const int*)  d_in[1];
    const int*   bat = (const int*)  d_in[2];
    const float* W1  = (const float*)d_in[3];
    const float* as1 = (const float*)d_in[4];
    const float* ad1 = (const float*)d_in[5];
    const float* b1  = (const float*)d_in[6];
    const float* W2  = (const float*)d_in[7];
    const float* as2 = (const float*)d_in[8];
    const float* ad2 = (const float*)d_in[9];
    const float* b2  = (const float*)d_in[10];
    const float* fcw = (const float*)d_in[11];
    const float* fcb = (const float*)d_in[12];
    float* out = (float*)d_out;

    int N    = in_sizes[0] / IN_DIM;
    int E    = in_sizes[1] / 2;
    int Etot = E + N;
    int nb   = (N + 255) / 256;
    const int TB = 256;
    dim3 gemm_grid(2, (N + 127) / 128);
    int gat_blocks = (N + 7) / 8;

    convert_edges_kernel<<<(2 * E + TB - 1) / TB, TB>>>(ei, 2 * E);
    convert_batch_kernel<<<(N + TB - 1) / TB, TB>>>(bat, N);

    init_kernel <<<nb, TB>>>(N);
    count_kernel<<<(E + TB - 1) / TB, TB>>>(E);
    scan1_kernel<<<nb, TB>>>(N);
    scan2_kernel<<<1, TB>>>(nb);
    scan3_kernel<<<nb, TB>>>(N, Etot);
    fill_kernel <<<(Etot + TB - 1) / TB, TB>>>(E, Etot);

    // layer 1
    gemm_tf32_kernel<<<gemm_grid, TB>>>(x, W1, N, 0);
    alphas_kernel   <<<(N * HEADS * 32 + TB - 1) / TB, TB>>>(as1, ad1, N);
    gat_warp        <<<gat_blocks, TB>>>(b1, N, 0);

    // layer 2
    gemm_tf32_kernel<<<gemm_grid, TB>>>(nullptr, W2, N, 1);
    alphas_kernel   <<<(N * HEADS * 32 + TB - 1) / TB, TB>>>(as2, ad2, N);
    gat_warp        <<<gat_blocks, TB>>>(b2, N, 1);

    // readout
    final_kernel<<<1, 64>>>(fcw, fcb, out);
}